// round 16
// baseline (speedup 1.0000x reference)
#include <cuda_runtime.h>
#include <cuda_bf16.h>
#include <cuda_fp16.h>
#include <cstdint>

// Problem constants
constexpr int cB  = 2;
constexpr int cS  = 2048;
constexpr int cE  = 1024;
constexpr int cH  = 16;
constexpr int cDK = 64;
constexpr int cBH = cB * cH;          // 32
constexpr int cBS = cB * cS;          // 4096

// ---------------- scratch (static device arrays) ----------------
__device__ __align__(16) __half g_Q[cBH * cS * cDK];           // fp16, pre-scaled by log2e/8
__device__ __align__(16) __half g_K[cBH * cS * cDK];           // fp16 single
__device__ __align__(16) __half g_V[cBH * cS * cDK];           // fp16 single
__device__ __align__(16) __half g_x[cBS * cE];                 // x fp16 single
__device__ __align__(16) __half g_a[cBS * cE];                 // attn output fp16 single
__device__ __align__(16) __half g_wf[4][cE * cE];              // Wt[n][k] fp16 single
__device__ float g_l[cBH * cS];                                // per-row 1/l
__device__ __align__(16) __half g_e[(size_t)cBH * cS * cS];    // unnormalized masked e (fp16)
__device__ __align__(16) uint64_t g_mbits[cS * (cS / 64)];     // bit-packed mask, 512 KB
__device__ float g_w[(size_t)cBH * cS * cS];                   // fallback weights buffer

// ---------------- static streams/events ----------------
struct HxStreams {
    cudaStream_t sA;
    cudaEvent_t eFork, eJoin, eAttn, eScale;
    HxStreams() {
        cudaStreamCreateWithFlags(&sA, cudaStreamNonBlocking);
        cudaEventCreateWithFlags(&eFork,  cudaEventDisableTiming);
        cudaEventCreateWithFlags(&eJoin,  cudaEventDisableTiming);
        cudaEventCreateWithFlags(&eAttn,  cudaEventDisableTiming);
        cudaEventCreateWithFlags(&eScale, cudaEventDisableTiming);
    }
};
static HxStreams g_hx;

// ---------------- helpers ----------------
__device__ __forceinline__ uint32_t smem_u32(const void* p) {
    uint32_t a;
    asm("{ .reg .u64 t; cvta.to.shared.u64 t, %1; cvt.u32.u64 %0, t; }" : "=r"(a) : "l"(p));
    return a;
}
__device__ __forceinline__ float ex2f(float x) {
    float y;
    asm("ex2.approx.f32 %0, %1;" : "=f"(y) : "f"(x));
    return y;
}
__device__ __forceinline__ void ldsm4(uint32_t r[4], uint32_t addr) {
    asm volatile("ldmatrix.sync.aligned.m8n8.x4.shared.b16 {%0,%1,%2,%3}, [%4];"
                 : "=r"(r[0]), "=r"(r[1]), "=r"(r[2]), "=r"(r[3]) : "r"(addr));
}
__device__ __forceinline__ void ldsm4t(uint32_t r[4], uint32_t addr) {
    asm volatile("ldmatrix.sync.aligned.m8n8.x4.trans.shared.b16 {%0,%1,%2,%3}, [%4];"
                 : "=r"(r[0]), "=r"(r[1]), "=r"(r[2]), "=r"(r[3]) : "r"(addr));
}
__device__ __forceinline__ void mma_f16(float d[4], const uint32_t a[4], const uint32_t b[2]) {
    asm volatile(
        "mma.sync.aligned.m16n8k16.row.col.f32.f16.f16.f32 "
        "{%0,%1,%2,%3}, {%4,%5,%6,%7}, {%8,%9}, {%0,%1,%2,%3};"
        : "+f"(d[0]), "+f"(d[1]), "+f"(d[2]), "+f"(d[3])
        : "r"(a[0]), "r"(a[1]), "r"(a[2]), "r"(a[3]), "r"(b[0]), "r"(b[1]));
}
__device__ __forceinline__ void cpa(uint32_t dst, const void* src) {
    asm volatile("cp.async.cg.shared.global [%0], [%1], 16;" :: "r"(dst), "l"(src));
}
__device__ __forceinline__ void cpa_commit() {
    asm volatile("cp.async.commit_group;" ::: "memory");
}
__device__ __forceinline__ void cpa_wait1() {
    asm volatile("cp.async.wait_group 1;" ::: "memory");
}
__device__ __forceinline__ void cpa_wait0() {
    asm volatile("cp.async.wait_group 0;" ::: "memory");
}

// ---------------- conversion kernels ----------------
__global__ __launch_bounds__(256) void conv_x(const float* __restrict__ src)
{
    int i = blockIdx.x * 256 + threadIdx.x;
    float4 v = ((const float4*)src)[i];
    __half2 a = __floats2half2_rn(v.x, v.y);
    __half2 b = __floats2half2_rn(v.z, v.w);
    ((uint2*)g_x)[i] = make_uint2(*(uint32_t*)&a, *(uint32_t*)&b);
}

__global__ __launch_bounds__(256) void conv_wt4(const float* __restrict__ W0,
                                                const float* __restrict__ W1,
                                                const float* __restrict__ W2,
                                                const float* __restrict__ W3)
{
    __shared__ float t[32][33];
    const int wsel = blockIdx.z;
    const float* W = (wsel == 0) ? W0 : (wsel == 1) ? W1 : (wsel == 2) ? W2 : W3;
    const int k0 = blockIdx.y * 32, n0 = blockIdx.x * 32;
    const int tx = threadIdx.x & 31, ty = threadIdx.x >> 5;
#pragma unroll
    for (int r = 0; r < 32; r += 8)
        t[ty + r][tx] = W[(size_t)(k0 + ty + r) * cE + n0 + tx];
    __syncthreads();
    __half* h = g_wf[wsel];
#pragma unroll
    for (int r = 0; r < 32; r += 8)
        h[(size_t)(n0 + ty + r) * cE + k0 + tx] = __float2half_rn(t[tx][ty + r]);
}

__global__ __launch_bounds__(256) void pack_mask(const int* __restrict__ mask)
{
    const int idx = blockIdx.x * 256 + threadIdx.x;
    const int row = idx >> 5, w = idx & 31;
    const int4* p = (const int4*)(mask + (size_t)row * cS + w * 64);
    uint64_t bits = 0;
#pragma unroll
    for (int j = 0; j < 16; ++j) {
        const int4 v = p[j];
        bits |= (uint64_t)(v.x != 0) << (j * 4 + 0);
        bits |= (uint64_t)(v.y != 0) << (j * 4 + 1);
        bits |= (uint64_t)(v.z != 0) << (j * 4 + 2);
        bits |= (uint64_t)(v.w != 0) << (j * 4 + 3);
    }
    g_mbits[idx] = bits;
}

// ---------------- fp16 HMMA GEMM core: K-stage 64 ----------------
constexpr int SP = 72;                         // halfs per row (64 + 8 pad)
constexpr int GT = 128 * SP * 2;               // 18432 B per tile
constexpr int GSTG = 2 * GT;                   // 36864 B per stage (A, B)
constexpr int GEMM_SMEM = 2 * GSTG;            // 73728 B (x2 CTAs = 147456 <= 228K)

__device__ __forceinline__ void gemm_core(char* smem, uint32_t sb,
                                          const __half* A, const __half* Bf,
                                          int m0, int n0, int tid, int wm, int wn, int lane,
                                          float acc[2][8][4])
{
    const __half* srcs[2] = {A, Bf};

    auto load_stage = [&](int kt, int buf) {
        const int k0 = kt * 64;
#pragma unroll
        for (int it = 0; it < 8; ++it) {
            const int q = tid + it * 256;              // 2048 16B-chunks
            const int tile = q >> 10, rem = q & 1023;
            const int r = rem >> 3, c = rem & 7;
            const int row = (tile == 0) ? (m0 + r) : (n0 + r);
            cpa(sb + buf * GSTG + tile * GT + (r * SP + c * 8) * 2,
                srcs[tile] + (size_t)row * cE + k0 + c * 8);
        }
        cpa_commit();
    };

    load_stage(0, 0);

    for (int kt = 0; kt < cE / 64; ++kt) {             // 16 stages
        const int buf = kt & 1;
        if (kt + 1 < cE / 64) { load_stage(kt + 1, buf ^ 1); cpa_wait1(); }
        else                  { cpa_wait0(); }
        __syncthreads();

        const uint32_t base = sb + buf * GSTG;
#pragma unroll
        for (int ks = 0; ks < 4; ++ks) {
            uint32_t af[2][4];
#pragma unroll
            for (int mb = 0; mb < 2; ++mb) {
                const int row = wm * 32 + mb * 16 + (lane & 15);
                const int ko  = ks * 16 + (lane >> 4) * 8;
                ldsm4(af[mb], base + (row * SP + ko) * 2);
            }
#pragma unroll
            for (int ntp = 0; ntp < 4; ++ntp) {
                const int row = wn * 64 + ntp * 16 + ((lane >> 4) & 1) * 8 + (lane & 7);
                const int ko  = ks * 16 + ((lane >> 3) & 1) * 8;
                uint32_t bf[4];
                ldsm4(bf, base + GT + (row * SP + ko) * 2);
#pragma unroll
                for (int h = 0; h < 2; ++h) {
                    const uint32_t bp[2] = {bf[h * 2], bf[h * 2 + 1]};
                    const int nt = ntp * 2 + h;
#pragma unroll
                    for (int mb = 0; mb < 2; ++mb)
                        mma_f16(acc[mb][nt], af[mb], bp);
                }
            }
        }
        __syncthreads();
    }
}

// ---------------- QKV projections: one launch, z = 0/1/2 ----------------
__global__ __launch_bounds__(256, 2) void gemm_qkv(const float* __restrict__ bq,
                                                   const float* __restrict__ bk,
                                                   const float* __restrict__ bv)
{
    extern __shared__ __align__(128) char smem[];
    const uint32_t sb = smem_u32(smem);
    const int tid = threadIdx.x, wid = tid >> 5, lane = tid & 31;
    const int m0 = blockIdx.y * 128, n0 = blockIdx.x * 128;
    const int wm = wid & 3, wn = wid >> 2;
    const int mode = blockIdx.z;
    const float* bias = (mode == 0) ? bq : (mode == 1) ? bk : bv;

    float acc[2][8][4] = {};
    gemm_core(smem, sb, g_x, g_wf[mode], m0, n0, tid, wm, wn, lane, acc);

    __half* dst = (mode == 0) ? g_Q : (mode == 1) ? g_K : g_V;
    const float sc = (mode == 0) ? 0.125f * 1.44269504088896340736f : 1.0f;

#pragma unroll
    for (int mb = 0; mb < 2; ++mb) {
#pragma unroll
        for (int nt = 0; nt < 8; ++nt) {
            const int r0  = m0 + wm * 32 + mb * 16 + (lane >> 2);
            const int col = n0 + wn * 64 + nt * 8 + (lane & 3) * 2;
            const float bv0 = bias[col], bv1 = bias[col + 1];
            const float v00 = (acc[mb][nt][0] + bv0) * sc, v01 = (acc[mb][nt][1] + bv1) * sc;
            const float v10 = (acc[mb][nt][2] + bv0) * sc, v11 = (acc[mb][nt][3] + bv1) * sc;
            const int hh = col >> 6, dd = col & 63;
#pragma unroll
            for (int rr = 0; rr < 2; ++rr) {
                const int m = r0 + rr * 8;
                const int bb = m >> 11, ss = m & 2047;
                const size_t idx = (((size_t)(bb * cH + hh)) * cS + ss) * cDK + dd;
                const __half2 hv = __floats2half2_rn(rr ? v10 : v00, rr ? v11 : v01);
                *(uint32_t*)&dst[idx] = *(const uint32_t*)&hv;
            }
        }
    }
}

// ---------------- output projection ----------------
__global__ __launch_bounds__(256, 2) void gemm_out(const float* __restrict__ bo,
                                                   float* __restrict__ pout)
{
    extern __shared__ __align__(128) char smem[];
    const uint32_t sb = smem_u32(smem);
    const int tid = threadIdx.x, wid = tid >> 5, lane = tid & 31;
    const int m0 = blockIdx.y * 128, n0 = blockIdx.x * 128;
    const int wm = wid & 3, wn = wid >> 2;

    float acc[2][8][4] = {};
    gemm_core(smem, sb, g_a, g_wf[3], m0, n0, tid, wm, wn, lane, acc);

#pragma unroll
    for (int mb = 0; mb < 2; ++mb) {
#pragma unroll
        for (int nt = 0; nt < 8; ++nt) {
            const int r0  = m0 + wm * 32 + mb * 16 + (lane >> 2);
            const int col = n0 + wn * 64 + nt * 8 + (lane & 3) * 2;
            const float bv0 = bo[col], bv1 = bo[col + 1];
            *(float2*)(pout + (size_t)r0 * cE + col) =
                make_float2(acc[mb][nt][0] + bv0, acc[mb][nt][1] + bv1);
            *(float2*)(pout + (size_t)(r0 + 8) * cE + col) =
                make_float2(acc[mb][nt][2] + bv0, acc[mb][nt][3] + bv1);
        }
    }
}

// ---------------- weights normalization (fp16 -> fp32) ----------------
__global__ __launch_bounds__(256) void scale_w(float* __restrict__ wp)
{
    const size_t i = (size_t)blockIdx.x * 256 + threadIdx.x;
    const float linv = g_l[i >> 9];
    const uint2 u = ((const uint2*)g_e)[i];
    const float2 fa = __half22float2(*(const __half2*)&u.x);
    const float2 fb = __half22float2(*(const __half2*)&u.y);
    ((float4*)wp)[i] = make_float4(fa.x * linv, fa.y * linv, fb.x * linv, fb.y * linv);
}

// ---------------- one-pass fp16 HMMA attention: 128-key stages ----------
constexpr int QP2 = 72;
constexpr uint32_t SQ   = 128 * QP2 * 2;             // 18432 (Q single)
constexpr uint32_t KV0  = SQ;                        // 18432
constexpr uint32_t KVA  = 128 * QP2 * 2;             // 18432 per array (128 keys)
constexpr uint32_t SKV  = 2 * KVA;                   // 36864 per stage (K, V)
constexpr uint32_t SUBOFF = 64 * QP2 * 2;            // 9216 (64-key sub-tile)
constexpr int ATTN_SMEM = (int)(KV0 + 2 * SKV);      // 92160 (x2 CTAs = 184320)
constexpr int NSTAGE = cS / 128;                     // 16

__device__ __forceinline__ void compute_S(uint32_t sb, uint32_t kbase,
                                          int wid, int lane, float s[8][4])
{
#pragma unroll
    for (int nt = 0; nt < 8; ++nt)
#pragma unroll
        for (int j = 0; j < 4; ++j) s[nt][j] = 0.f;
#pragma unroll
    for (int kb = 0; kb < 4; ++kb) {
        const int qrow = wid * 16 + (lane & 15);
        const int ko   = kb * 16 + (lane >> 4) * 8;
        uint32_t qf[4];
        ldsm4(qf, sb + (qrow * QP2 + ko) * 2);
#pragma unroll
        for (int ntp = 0; ntp < 4; ++ntp) {
            const int krow = ntp * 16 + ((lane >> 4) & 1) * 8 + (lane & 7);
            const int kko  = kb * 16 + ((lane >> 3) & 1) * 8;
            uint32_t kf[4];
            ldsm4(kf, kbase + (krow * QP2 + kko) * 2);
#pragma unroll
            for (int h = 0; h < 2; ++h) {
                const uint32_t bp[2] = {kf[h * 2], kf[h * 2 + 1]};
                mma_f16(s[ntp * 2 + h], qf, bp);
            }
        }
    }
}

__global__ __launch_bounds__(256, 2) void attn_mma()
{
    extern __shared__ __align__(128) char smem[];
    const uint32_t sb = smem_u32(smem);
    const int tid = threadIdx.x, wid = tid >> 5, lane = tid & 31;
    const int bh = blockIdx.y, q0 = blockIdx.x * 128;
    const size_t base = (size_t)bh * cS * cDK;
    __half* ep = g_e + (size_t)bh * cS * cS;

    // Q tile (fp16 single): 1024 16B-chunks
#pragma unroll
    for (int it = 0; it < 4; ++it) {
        const int q = tid + it * 256;
        const int r = q >> 3, c = q & 7;
        cpa(sb + (r * QP2 + c * 8) * 2,
            g_Q + base + (size_t)(q0 + r) * cDK + c * 8);
    }
    cpa_commit();

    const __half* kvsrc[2] = {g_K, g_V};
    auto load_kv = [&](int st, int buf) {
#pragma unroll
        for (int it = 0; it < 8; ++it) {
            const int q = tid + it * 256;              // 2048 chunks: 2 arrays x 1024
            const int arr = q >> 10, rem = q & 1023, r = rem >> 3, c = rem & 7;
            cpa(sb + KV0 + buf * SKV + arr * KVA + (r * QP2 + c * 8) * 2,
                kvsrc[arr] + base + (size_t)(st * 128 + r) * cDK + c * 8);
        }
        cpa_commit();
    };
    load_kv(0, 0);

    float l0r = 0.f, l1r = 0.f;
    float o[8][4] = {};
    const int qr0 = q0 + wid * 16 + (lane >> 2);

    for (int st = 0; st < NSTAGE; ++st) {
        const int buf = st & 1;
        if (st + 1 < NSTAGE) { load_kv(st + 1, buf ^ 1); cpa_wait1(); }
        else                 { cpa_wait0(); }
        __syncthreads();

#pragma unroll
        for (int sub = 0; sub < 2; ++sub) {
            const uint32_t kbase = sb + KV0 + buf * SKV + sub * SUBOFF;
            const uint32_t vbase = sb + KV0 + buf * SKV + KVA + sub * SUBOFF;
            const int ks64 = st * 2 + sub;

            float s[8][4];
            compute_S(sb, kbase, wid, lane, s);

            const uint64_t mb0 = g_mbits[(size_t)qr0 * (cS / 64) + ks64];
            const uint64_t mb1 = g_mbits[(size_t)(qr0 + 8) * (cS / 64) + ks64];

            // exp + mask + build W fragments (stores deferred past the MMAs)
            uint32_t wf[4][4];
#pragma unroll
            for (int nt = 0; nt < 8; ++nt) {
                const int sh = nt * 8 + (lane & 3) * 2;
                const float e00 = ex2f(s[nt][0]);
                const float e01 = ex2f(s[nt][1]);
                const float e10 = ex2f(s[nt][2]);
                const float e11 = ex2f(s[nt][3]);
                l0r += e00 + e01;
                l1r += e10 + e11;
                const __half2 a0 = __floats2half2_rn(((mb0 >> sh) & 1) ? e00 : 0.f,
                                                     ((mb0 >> (sh + 1)) & 1) ? e01 : 0.f);
                const __half2 a1 = __floats2half2_rn(((mb1 >> sh) & 1) ? e10 : 0.f,
                                                     ((mb1 >> (sh + 1)) & 1) ? e11 : 0.f);
                const int kb = nt >> 1, hf = nt & 1;
                wf[kb][hf * 2]     = *(const uint32_t*)&a0;
                wf[kb][hf * 2 + 1] = *(const uint32_t*)&a1;
            }

            // O += W @ V
#pragma unroll
            for (int kb = 0; kb < 4; ++kb) {
#pragma unroll
                for (int ntp = 0; ntp < 4; ++ntp) {
                    const int vrow = kb * 16 + ((lane >> 3) & 1) * 8 + (lane & 7);
                    const int vcol = ntp * 16 + ((lane >> 4) & 1) * 8;
                    uint32_t vf[4];
                    ldsm4t(vf, vbase + (vrow * QP2 + vcol) * 2);
#pragma unroll
                    for (int h = 0; h < 2; ++h) {
                        const uint32_t bp[2] = {vf[h * 2], vf[h * 2 + 1]};
                        mma_f16(o[ntp * 2 + h], wf[kb], bp);
                    }
                }
            }

            // weight stores (fire-and-forget)
            const int kt0 = ks64 * 64;
#pragma unroll
            for (int nt = 0; nt < 8; ++nt) {
                const int col = kt0 + nt * 8 + (lane & 3) * 2;
                const int kb = nt >> 1, hf = nt & 1;
                *(uint32_t*)(ep + (size_t)qr0 * cS + col)       = wf[kb][hf * 2];
                *(uint32_t*)(ep + (size_t)(qr0 + 8) * cS + col) = wf[kb][hf * 2 + 1];
            }
        }
        __syncthreads();
    }

    l0r += __shfl_xor_sync(0xffffffffu, l0r, 1);
    l0r += __shfl_xor_sync(0xffffffffu, l0r, 2);
    l1r += __shfl_xor_sync(0xffffffffu, l1r, 1);
    l1r += __shfl_xor_sync(0xffffffffu, l1r, 2);
    const float linv0 = 1.0f / l0r, linv1 = 1.0f / l1r;

    const int bb = bh >> 4, hh = bh & 15;
#pragma unroll
    for (int nt = 0; nt < 8; ++nt) {
        const int dk = nt * 8 + (lane & 3) * 2;
        const size_t i0 = ((size_t)bb * cS + qr0) * cE + hh * cDK + dk;
        const size_t i1 = ((size_t)bb * cS + qr0 + 8) * cE + hh * cDK + dk;
        const __half2 h0 = __floats2half2_rn(o[nt][0] * linv0, o[nt][1] * linv0);
        const __half2 h1 = __floats2half2_rn(o[nt][2] * linv1, o[nt][3] * linv1);
        *(uint32_t*)&g_a[i0] = *(const uint32_t*)&h0;
        *(uint32_t*)&g_a[i1] = *(const uint32_t*)&h1;
    }
    if ((lane & 3) == 0) {
        g_l[bh * cS + qr0]     = linv0;
        g_l[bh * cS + qr0 + 8] = linv1;
    }
}

// ---------------------------------------------------------------------------
extern "C" void kernel_launch(void* const* d_in, const int* in_sizes, int n_in,
                              void* d_out, int out_size)
{
    const float* x    = (const float*)d_in[0];
    const int*   mask = (const int*)  d_in[1];
    const float* Wq   = (const float*)d_in[2];
    const float* bq   = (const float*)d_in[3];
    const float* Wk   = (const float*)d_in[4];
    const float* bk   = (const float*)d_in[5];
    const float* Wv   = (const float*)d_in[6];
    const float* bv   = (const float*)d_in[7];
    const float* Wo   = (const float*)d_in[8];
    const float* bo   = (const float*)d_in[9];
    float* out = (float*)d_out;

    cudaFuncSetAttribute((const void*)attn_mma,
                         cudaFuncAttributeMaxDynamicSharedMemorySize, ATTN_SMEM);
    cudaFuncSetAttribute((const void*)attn_mma,
                         cudaFuncAttributePreferredSharedMemoryCarveout, 100);
    cudaFuncSetAttribute((const void*)gemm_qkv,
                         cudaFuncAttributeMaxDynamicSharedMemorySize, GEMM_SMEM);
    cudaFuncSetAttribute((const void*)gemm_qkv,
                         cudaFuncAttributePreferredSharedMemoryCarveout, 100);
    cudaFuncSetAttribute((const void*)gemm_out,
                         cudaFuncAttributeMaxDynamicSharedMemorySize, GEMM_SMEM);
    cudaFuncSetAttribute((const void*)gemm_out,
                         cudaFuncAttributePreferredSharedMemoryCarveout, 100);

    const long long out_elems = (long long)cB * cS * cE;
    const int use_dout = ((long long)out_size > out_elems) ? 1 : 0;
    float* wtarget = use_dout ? (out + out_elems) : g_w;

    // --- fork: conv_x on origin || (conv_wt4 -> pack_mask) on sA ---
    cudaEventRecord(g_hx.eFork, 0);
    cudaStreamWaitEvent(g_hx.sA, g_hx.eFork, 0);

    conv_x<<<cBS * cE / 4 / 256, 256>>>(x);
    conv_wt4<<<dim3(cE / 32, cE / 32, 4), 256, 0, g_hx.sA>>>(Wq, Wk, Wv, Wo);
    pack_mask<<<cS * (cS / 64) / 256, 256, 0, g_hx.sA>>>(mask);

    cudaEventRecord(g_hx.eJoin, g_hx.sA);
    cudaStreamWaitEvent(0, g_hx.eJoin, 0);

    // --- serial spine: qkv -> attn ---
    gemm_qkv<<<dim3(cE / 128, cBS / 128, 3), 256, GEMM_SMEM>>>(bq, bk, bv);
    attn_mma<<<dim3(cS / 128, cBH), 256, ATTN_SMEM>>>();

    // --- fork: scale_w on sA || gemm_out on origin ---
    cudaEventRecord(g_hx.eAttn, 0);
    cudaStreamWaitEvent(g_hx.sA, g_hx.eAttn, 0);

    const long long wq4 = (long long)cBH * cS * cS / 4;
    scale_w<<<(unsigned)(wq4 / 256), 256, 0, g_hx.sA>>>(wtarget);
    gemm_out<<<dim3(cE / 128, cBS / 128), 256, GEMM_SMEM>>>(bo, out);

    cudaEventRecord(g_hx.eScale, g_hx.sA);
    cudaStreamWaitEvent(0, g_hx.eScale, 0);
}

// round 17
// speedup vs baseline: 1.0545x; 1.0545x over previous
#include <cuda_runtime.h>
#include <cuda_bf16.h>
#include <cuda_fp16.h>
#include <cstdint>

// Problem constants
constexpr int cB  = 2;
constexpr int cS  = 2048;
constexpr int cE  = 1024;
constexpr int cH  = 16;
constexpr int cDK = 64;
constexpr int cBH = cB * cH;          // 32
constexpr int cBS = cB * cS;          // 4096

// ---------------- scratch (static device arrays) ----------------
__device__ __align__(16) __half g_Q[cBH * cS * cDK];           // fp16, pre-scaled by log2e/8
__device__ __align__(16) __half g_K[cBH * cS * cDK];           // fp16 single
__device__ __align__(16) __half g_V[cBH * cS * cDK];           // fp16 single
__device__ __align__(16) __half g_x[cBS * cE];                 // x fp16 single
__device__ __align__(16) __half g_a[cBS * cE];                 // attn output fp16 single
__device__ __align__(16) __half g_wf[4][cE * cE];              // Wt[n][k] fp16 single
__device__ float g_l[cBH * cS];                                // per-row 1/l
__device__ __align__(16) __half g_e[(size_t)cBH * cS * cS];    // unnormalized masked e (fp16)
__device__ __align__(16) uint64_t g_mbits[cS * (cS / 64)];     // bit-packed mask, 512 KB
__device__ float g_w[(size_t)cBH * cS * cS];                   // fallback weights buffer

// ---------------- static streams/events ----------------
struct HxStreams {
    cudaStream_t sA;
    cudaEvent_t eFork, eJoin, eAttn, eScale;
    HxStreams() {
        cudaStreamCreateWithFlags(&sA, cudaStreamNonBlocking);
        cudaEventCreateWithFlags(&eFork,  cudaEventDisableTiming);
        cudaEventCreateWithFlags(&eJoin,  cudaEventDisableTiming);
        cudaEventCreateWithFlags(&eAttn,  cudaEventDisableTiming);
        cudaEventCreateWithFlags(&eScale, cudaEventDisableTiming);
    }
};
static HxStreams g_hx;

// ---------------- helpers ----------------
__device__ __forceinline__ uint32_t smem_u32(const void* p) {
    uint32_t a;
    asm("{ .reg .u64 t; cvta.to.shared.u64 t, %1; cvt.u32.u64 %0, t; }" : "=r"(a) : "l"(p));
    return a;
}
__device__ __forceinline__ float ex2f(float x) {
    float y;
    asm("ex2.approx.f32 %0, %1;" : "=f"(y) : "f"(x));
    return y;
}
__device__ __forceinline__ void ldsm4(uint32_t r[4], uint32_t addr) {
    asm volatile("ldmatrix.sync.aligned.m8n8.x4.shared.b16 {%0,%1,%2,%3}, [%4];"
                 : "=r"(r[0]), "=r"(r[1]), "=r"(r[2]), "=r"(r[3]) : "r"(addr));
}
__device__ __forceinline__ void ldsm4t(uint32_t r[4], uint32_t addr) {
    asm volatile("ldmatrix.sync.aligned.m8n8.x4.trans.shared.b16 {%0,%1,%2,%3}, [%4];"
                 : "=r"(r[0]), "=r"(r[1]), "=r"(r[2]), "=r"(r[3]) : "r"(addr));
}
__device__ __forceinline__ void mma_f16(float d[4], const uint32_t a[4], const uint32_t b[2]) {
    asm volatile(
        "mma.sync.aligned.m16n8k16.row.col.f32.f16.f16.f32 "
        "{%0,%1,%2,%3}, {%4,%5,%6,%7}, {%8,%9}, {%0,%1,%2,%3};"
        : "+f"(d[0]), "+f"(d[1]), "+f"(d[2]), "+f"(d[3])
        : "r"(a[0]), "r"(a[1]), "r"(a[2]), "r"(a[3]), "r"(b[0]), "r"(b[1]));
}
__device__ __forceinline__ void cpa(uint32_t dst, const void* src) {
    asm volatile("cp.async.cg.shared.global [%0], [%1], 16;" :: "r"(dst), "l"(src));
}
__device__ __forceinline__ void cpa_commit() {
    asm volatile("cp.async.commit_group;" ::: "memory");
}
__device__ __forceinline__ void cpa_wait1() {
    asm volatile("cp.async.wait_group 1;" ::: "memory");
}
__device__ __forceinline__ void cpa_wait0() {
    asm volatile("cp.async.wait_group 0;" ::: "memory");
}

// ---------------- conversion kernels ----------------
__global__ __launch_bounds__(256) void conv_x(const float* __restrict__ src)
{
    int i = blockIdx.x * 256 + threadIdx.x;
    float4 v = ((const float4*)src)[i];
    __half2 a = __floats2half2_rn(v.x, v.y);
    __half2 b = __floats2half2_rn(v.z, v.w);
    ((uint2*)g_x)[i] = make_uint2(*(uint32_t*)&a, *(uint32_t*)&b);
}

__global__ __launch_bounds__(256) void conv_wt4(const float* __restrict__ W0,
                                                const float* __restrict__ W1,
                                                const float* __restrict__ W2,
                                                const float* __restrict__ W3)
{
    __shared__ float t[32][33];
    const int wsel = blockIdx.z;
    const float* W = (wsel == 0) ? W0 : (wsel == 1) ? W1 : (wsel == 2) ? W2 : W3;
    const int k0 = blockIdx.y * 32, n0 = blockIdx.x * 32;
    const int tx = threadIdx.x & 31, ty = threadIdx.x >> 5;
#pragma unroll
    for (int r = 0; r < 32; r += 8)
        t[ty + r][tx] = W[(size_t)(k0 + ty + r) * cE + n0 + tx];
    __syncthreads();
    __half* h = g_wf[wsel];
#pragma unroll
    for (int r = 0; r < 32; r += 8)
        h[(size_t)(n0 + ty + r) * cE + k0 + tx] = __float2half_rn(t[tx][ty + r]);
}

__global__ __launch_bounds__(256) void pack_mask(const int* __restrict__ mask)
{
    const int idx = blockIdx.x * 256 + threadIdx.x;
    const int row = idx >> 5, w = idx & 31;
    const int4* p = (const int4*)(mask + (size_t)row * cS + w * 64);
    uint64_t bits = 0;
#pragma unroll
    for (int j = 0; j < 16; ++j) {
        const int4 v = p[j];
        bits |= (uint64_t)(v.x != 0) << (j * 4 + 0);
        bits |= (uint64_t)(v.y != 0) << (j * 4 + 1);
        bits |= (uint64_t)(v.z != 0) << (j * 4 + 2);
        bits |= (uint64_t)(v.w != 0) << (j * 4 + 3);
    }
    g_mbits[idx] = bits;
}

// ---------------- fp16 HMMA GEMM core: K-stage 64 (round-16 win) ----------
constexpr int SP = 72;                         // halfs per row (64 + 8 pad)
constexpr int GT = 128 * SP * 2;               // 18432 B per tile
constexpr int GSTG = 2 * GT;                   // 36864 B per stage (A, B)
constexpr int GEMM_SMEM = 2 * GSTG;            // 73728 B (x2 CTAs = 147456 <= 228K)

__device__ __forceinline__ void gemm_core(char* smem, uint32_t sb,
                                          const __half* A, const __half* Bf,
                                          int m0, int n0, int tid, int wm, int wn, int lane,
                                          float acc[2][8][4])
{
    const __half* srcs[2] = {A, Bf};

    auto load_stage = [&](int kt, int buf) {
        const int k0 = kt * 64;
#pragma unroll
        for (int it = 0; it < 8; ++it) {
            const int q = tid + it * 256;              // 2048 16B-chunks
            const int tile = q >> 10, rem = q & 1023;
            const int r = rem >> 3, c = rem & 7;
            const int row = (tile == 0) ? (m0 + r) : (n0 + r);
            cpa(sb + buf * GSTG + tile * GT + (r * SP + c * 8) * 2,
                srcs[tile] + (size_t)row * cE + k0 + c * 8);
        }
        cpa_commit();
    };

    load_stage(0, 0);

    for (int kt = 0; kt < cE / 64; ++kt) {             // 16 stages
        const int buf = kt & 1;
        if (kt + 1 < cE / 64) { load_stage(kt + 1, buf ^ 1); cpa_wait1(); }
        else                  { cpa_wait0(); }
        __syncthreads();

        const uint32_t base = sb + buf * GSTG;
#pragma unroll
        for (int ks = 0; ks < 4; ++ks) {
            uint32_t af[2][4];
#pragma unroll
            for (int mb = 0; mb < 2; ++mb) {
                const int row = wm * 32 + mb * 16 + (lane & 15);
                const int ko  = ks * 16 + (lane >> 4) * 8;
                ldsm4(af[mb], base + (row * SP + ko) * 2);
            }
#pragma unroll
            for (int ntp = 0; ntp < 4; ++ntp) {
                const int row = wn * 64 + ntp * 16 + ((lane >> 4) & 1) * 8 + (lane & 7);
                const int ko  = ks * 16 + ((lane >> 3) & 1) * 8;
                uint32_t bf[4];
                ldsm4(bf, base + GT + (row * SP + ko) * 2);
#pragma unroll
                for (int h = 0; h < 2; ++h) {
                    const uint32_t bp[2] = {bf[h * 2], bf[h * 2 + 1]};
                    const int nt = ntp * 2 + h;
#pragma unroll
                    for (int mb = 0; mb < 2; ++mb)
                        mma_f16(acc[mb][nt], af[mb], bp);
                }
            }
        }
        __syncthreads();
    }
}

// ---------------- QKV projections: one launch, z = 0/1/2 ----------------
__global__ __launch_bounds__(256, 2) void gemm_qkv(const float* __restrict__ bq,
                                                   const float* __restrict__ bk,
                                                   const float* __restrict__ bv)
{
    extern __shared__ __align__(128) char smem[];
    const uint32_t sb = smem_u32(smem);
    const int tid = threadIdx.x, wid = tid >> 5, lane = tid & 31;
    const int m0 = blockIdx.y * 128, n0 = blockIdx.x * 128;
    const int wm = wid & 3, wn = wid >> 2;
    const int mode = blockIdx.z;
    const float* bias = (mode == 0) ? bq : (mode == 1) ? bk : bv;

    float acc[2][8][4] = {};
    gemm_core(smem, sb, g_x, g_wf[mode], m0, n0, tid, wm, wn, lane, acc);

    __half* dst = (mode == 0) ? g_Q : (mode == 1) ? g_K : g_V;
    const float sc = (mode == 0) ? 0.125f * 1.44269504088896340736f : 1.0f;

#pragma unroll
    for (int mb = 0; mb < 2; ++mb) {
#pragma unroll
        for (int nt = 0; nt < 8; ++nt) {
            const int r0  = m0 + wm * 32 + mb * 16 + (lane >> 2);
            const int col = n0 + wn * 64 + nt * 8 + (lane & 3) * 2;
            const float bv0 = bias[col], bv1 = bias[col + 1];
            const float v00 = (acc[mb][nt][0] + bv0) * sc, v01 = (acc[mb][nt][1] + bv1) * sc;
            const float v10 = (acc[mb][nt][2] + bv0) * sc, v11 = (acc[mb][nt][3] + bv1) * sc;
            const int hh = col >> 6, dd = col & 63;
#pragma unroll
            for (int rr = 0; rr < 2; ++rr) {
                const int m = r0 + rr * 8;
                const int bb = m >> 11, ss = m & 2047;
                const size_t idx = (((size_t)(bb * cH + hh)) * cS + ss) * cDK + dd;
                const __half2 hv = __floats2half2_rn(rr ? v10 : v00, rr ? v11 : v01);
                *(uint32_t*)&dst[idx] = *(const uint32_t*)&hv;
            }
        }
    }
}

// ---------------- output projection ----------------
__global__ __launch_bounds__(256, 2) void gemm_out(const float* __restrict__ bo,
                                                   float* __restrict__ pout)
{
    extern __shared__ __align__(128) char smem[];
    const uint32_t sb = smem_u32(smem);
    const int tid = threadIdx.x, wid = tid >> 5, lane = tid & 31;
    const int m0 = blockIdx.y * 128, n0 = blockIdx.x * 128;
    const int wm = wid & 3, wn = wid >> 2;

    float acc[2][8][4] = {};
    gemm_core(smem, sb, g_a, g_wf[3], m0, n0, tid, wm, wn, lane, acc);

#pragma unroll
    for (int mb = 0; mb < 2; ++mb) {
#pragma unroll
        for (int nt = 0; nt < 8; ++nt) {
            const int r0  = m0 + wm * 32 + mb * 16 + (lane >> 2);
            const int col = n0 + wn * 64 + nt * 8 + (lane & 3) * 2;
            const float bv0 = bo[col], bv1 = bo[col + 1];
            *(float2*)(pout + (size_t)r0 * cE + col) =
                make_float2(acc[mb][nt][0] + bv0, acc[mb][nt][1] + bv1);
            *(float2*)(pout + (size_t)(r0 + 8) * cE + col) =
                make_float2(acc[mb][nt][2] + bv0, acc[mb][nt][3] + bv1);
        }
    }
}

// ---------------- weights normalization (fp16 -> fp32) ----------------
__global__ __launch_bounds__(256) void scale_w(float* __restrict__ wp)
{
    const size_t i = (size_t)blockIdx.x * 256 + threadIdx.x;
    const float linv = g_l[i >> 9];
    const uint2 u = ((const uint2*)g_e)[i];
    const float2 fa = __half22float2(*(const __half2*)&u.x);
    const float2 fb = __half22float2(*(const __half2*)&u.y);
    ((float4*)wp)[i] = make_float4(fa.x * linv, fa.y * linv, fb.x * linv, fb.y * linv);
}

// ---------------- one-pass fp16 HMMA attention: 64-key stages (round 15) --
constexpr int QP2 = 72;
constexpr uint32_t SQ   = 128 * QP2 * 2;             // 18432 (Q single)
constexpr uint32_t KV0  = SQ;                        // 18432
constexpr uint32_t KVA  = 64 * QP2 * 2;              // 9216 per array
constexpr uint32_t SKV  = 2 * KVA;                   // 18432 per stage (K, V)
constexpr int ATTN_SMEM = (int)(KV0 + 2 * SKV);      // 55296
constexpr int NSTEP = cS / 64;                       // 32

__device__ __forceinline__ void compute_S(uint32_t sb, uint32_t kbase,
                                          int wid, int lane, float s[8][4])
{
#pragma unroll
    for (int nt = 0; nt < 8; ++nt)
#pragma unroll
        for (int j = 0; j < 4; ++j) s[nt][j] = 0.f;
#pragma unroll
    for (int kb = 0; kb < 4; ++kb) {
        const int qrow = wid * 16 + (lane & 15);
        const int ko   = kb * 16 + (lane >> 4) * 8;
        uint32_t qf[4];
        ldsm4(qf, sb + (qrow * QP2 + ko) * 2);
#pragma unroll
        for (int ntp = 0; ntp < 4; ++ntp) {
            const int krow = ntp * 16 + ((lane >> 4) & 1) * 8 + (lane & 7);
            const int kko  = kb * 16 + ((lane >> 3) & 1) * 8;
            uint32_t kf[4];
            ldsm4(kf, kbase + (krow * QP2 + kko) * 2);
#pragma unroll
            for (int h = 0; h < 2; ++h) {
                const uint32_t bp[2] = {kf[h * 2], kf[h * 2 + 1]};
                mma_f16(s[ntp * 2 + h], qf, bp);
            }
        }
    }
}

__global__ __launch_bounds__(256, 2) void attn_mma()
{
    extern __shared__ __align__(128) char smem[];
    const uint32_t sb = smem_u32(smem);
    const int tid = threadIdx.x, wid = tid >> 5, lane = tid & 31;
    const int bh = blockIdx.y, q0 = blockIdx.x * 128;
    const size_t base = (size_t)bh * cS * cDK;
    __half* ep = g_e + (size_t)bh * cS * cS;

    // Q tile (fp16 single): 1024 16B-chunks
#pragma unroll
    for (int it = 0; it < 4; ++it) {
        const int q = tid + it * 256;
        const int r = q >> 3, c = q & 7;
        cpa(sb + (r * QP2 + c * 8) * 2,
            g_Q + base + (size_t)(q0 + r) * cDK + c * 8);
    }
    cpa_commit();

    const __half* kvsrc[2] = {g_K, g_V};
    auto load_kv = [&](int ks, int buf) {
#pragma unroll
        for (int it = 0; it < 4; ++it) {
            const int q = tid + it * 256;              // 1024 chunks: 2 arrays x 512
            const int arr = q >> 9, rem = q & 511, r = rem >> 3, c = rem & 7;
            cpa(sb + KV0 + buf * SKV + arr * KVA + (r * QP2 + c * 8) * 2,
                kvsrc[arr] + base + (size_t)(ks * 64 + r) * cDK + c * 8);
        }
        cpa_commit();
    };
    load_kv(0, 0);

    float l0r = 0.f, l1r = 0.f;
    float o[8][4] = {};
    const int qr0 = q0 + wid * 16 + (lane >> 2);

    for (int ks = 0; ks < NSTEP; ++ks) {
        const int buf = ks & 1;
        if (ks + 1 < NSTEP) { load_kv(ks + 1, buf ^ 1); cpa_wait1(); }
        else                { cpa_wait0(); }
        __syncthreads();

        const uint32_t kbase = sb + KV0 + buf * SKV;
        float s[8][4];
        compute_S(sb, kbase, wid, lane, s);

        const uint64_t mb0 = g_mbits[(size_t)qr0 * (cS / 64) + ks];
        const uint64_t mb1 = g_mbits[(size_t)(qr0 + 8) * (cS / 64) + ks];

        // exp + mask + build W fragments (weight stores deferred past MMAs)
        uint32_t wf[4][4];
#pragma unroll
        for (int nt = 0; nt < 8; ++nt) {
            const int sh = nt * 8 + (lane & 3) * 2;
            const float e00 = ex2f(s[nt][0]);
            const float e01 = ex2f(s[nt][1]);
            const float e10 = ex2f(s[nt][2]);
            const float e11 = ex2f(s[nt][3]);
            l0r += e00 + e01;
            l1r += e10 + e11;
            const __half2 a0 = __floats2half2_rn(((mb0 >> sh) & 1) ? e00 : 0.f,
                                                 ((mb0 >> (sh + 1)) & 1) ? e01 : 0.f);
            const __half2 a1 = __floats2half2_rn(((mb1 >> sh) & 1) ? e10 : 0.f,
                                                 ((mb1 >> (sh + 1)) & 1) ? e11 : 0.f);
            const int kb = nt >> 1, hf = nt & 1;
            wf[kb][hf * 2]     = *(const uint32_t*)&a0;
            wf[kb][hf * 2 + 1] = *(const uint32_t*)&a1;
        }

        // O += W @ V  (fp16 x fp16 single)
#pragma unroll
        for (int kb = 0; kb < 4; ++kb) {
#pragma unroll
            for (int ntp = 0; ntp < 4; ++ntp) {
                const int vrow = kb * 16 + ((lane >> 3) & 1) * 8 + (lane & 7);
                const int vcol = ntp * 16 + ((lane >> 4) & 1) * 8;
                uint32_t vf[4];
                ldsm4t(vf, kbase + KVA + (vrow * QP2 + vcol) * 2);
#pragma unroll
                for (int h = 0; h < 2; ++h) {
                    const uint32_t bp[2] = {vf[h * 2], vf[h * 2 + 1]};
                    mma_f16(o[ntp * 2 + h], wf[kb], bp);
                }
            }
        }

        // weight stores (fire-and-forget, after tensor work issued)
        const int kt0 = ks * 64;
#pragma unroll
        for (int nt = 0; nt < 8; ++nt) {
            const int col = kt0 + nt * 8 + (lane & 3) * 2;
            const int kb = nt >> 1, hf = nt & 1;
            *(uint32_t*)(ep + (size_t)qr0 * cS + col)       = wf[kb][hf * 2];
            *(uint32_t*)(ep + (size_t)(qr0 + 8) * cS + col) = wf[kb][hf * 2 + 1];
        }
        __syncthreads();
    }

    l0r += __shfl_xor_sync(0xffffffffu, l0r, 1);
    l0r += __shfl_xor_sync(0xffffffffu, l0r, 2);
    l1r += __shfl_xor_sync(0xffffffffu, l1r, 1);
    l1r += __shfl_xor_sync(0xffffffffu, l1r, 2);
    const float linv0 = 1.0f / l0r, linv1 = 1.0f / l1r;

    // O epilogue: fp16 single into [B,S,E]
    const int bb = bh >> 4, hh = bh & 15;
#pragma unroll
    for (int nt = 0; nt < 8; ++nt) {
        const int dk = nt * 8 + (lane & 3) * 2;
        const size_t i0 = ((size_t)bb * cS + qr0) * cE + hh * cDK + dk;
        const size_t i1 = ((size_t)bb * cS + qr0 + 8) * cE + hh * cDK + dk;
        const __half2 h0 = __floats2half2_rn(o[nt][0] * linv0, o[nt][1] * linv0);
        const __half2 h1 = __floats2half2_rn(o[nt][2] * linv1, o[nt][3] * linv1);
        *(uint32_t*)&g_a[i0] = *(const uint32_t*)&h0;
        *(uint32_t*)&g_a[i1] = *(const uint32_t*)&h1;
    }
    if ((lane & 3) == 0) {
        g_l[bh * cS + qr0]     = linv0;
        g_l[bh * cS + qr0 + 8] = linv1;
    }
}

// ---------------------------------------------------------------------------
extern "C" void kernel_launch(void* const* d_in, const int* in_sizes, int n_in,
                              void* d_out, int out_size)
{
    const float* x    = (const float*)d_in[0];
    const int*   mask = (const int*)  d_in[1];
    const float* Wq   = (const float*)d_in[2];
    const float* bq   = (const float*)d_in[3];
    const float* Wk   = (const float*)d_in[4];
    const float* bk   = (const float*)d_in[5];
    const float* Wv   = (const float*)d_in[6];
    const float* bv   = (const float*)d_in[7];
    const float* Wo   = (const float*)d_in[8];
    const float* bo   = (const float*)d_in[9];
    float* out = (float*)d_out;

    cudaFuncSetAttribute((const void*)attn_mma,
                         cudaFuncAttributeMaxDynamicSharedMemorySize, ATTN_SMEM);
    cudaFuncSetAttribute((const void*)attn_mma,
                         cudaFuncAttributePreferredSharedMemoryCarveout, 100);
    cudaFuncSetAttribute((const void*)gemm_qkv,
                         cudaFuncAttributeMaxDynamicSharedMemorySize, GEMM_SMEM);
    cudaFuncSetAttribute((const void*)gemm_qkv,
                         cudaFuncAttributePreferredSharedMemoryCarveout, 100);
    cudaFuncSetAttribute((const void*)gemm_out,
                         cudaFuncAttributeMaxDynamicSharedMemorySize, GEMM_SMEM);
    cudaFuncSetAttribute((const void*)gemm_out,
                         cudaFuncAttributePreferredSharedMemoryCarveout, 100);

    const long long out_elems = (long long)cB * cS * cE;
    const int use_dout = ((long long)out_size > out_elems) ? 1 : 0;
    float* wtarget = use_dout ? (out + out_elems) : g_w;

    // --- fork: conv_x on origin || (conv_wt4 -> pack_mask) on sA ---
    cudaEventRecord(g_hx.eFork, 0);
    cudaStreamWaitEvent(g_hx.sA, g_hx.eFork, 0);

    conv_x<<<cBS * cE / 4 / 256, 256>>>(x);
    conv_wt4<<<dim3(cE / 32, cE / 32, 4), 256, 0, g_hx.sA>>>(Wq, Wk, Wv, Wo);
    pack_mask<<<cS * (cS / 64) / 256, 256, 0, g_hx.sA>>>(mask);

    cudaEventRecord(g_hx.eJoin, g_hx.sA);
    cudaStreamWaitEvent(0, g_hx.eJoin, 0);

    // --- serial spine: qkv -> attn ---
    gemm_qkv<<<dim3(cE / 128, cBS / 128, 3), 256, GEMM_SMEM>>>(bq, bk, bv);
    attn_mma<<<dim3(cS / 128, cBH), 256, ATTN_SMEM>>>();

    // --- fork: scale_w on sA || gemm_out on origin ---
    cudaEventRecord(g_hx.eAttn, 0);
    cudaStreamWaitEvent(g_hx.sA, g_hx.eAttn, 0);

    const long long wq4 = (long long)cBH * cS * cS / 4;
    scale_w<<<(unsigned)(wq4 / 256), 256, 0, g_hx.sA>>>(wtarget);
    gemm_out<<<dim3(cE / 128, cBS / 128), 256, GEMM_SMEM>>>(bo, out);

    cudaEventRecord(g_hx.eScale, g_hx.sA);
    cudaStreamWaitEvent(0, g_hx.eScale, 0);
}